// round 5
// baseline (speedup 1.0000x reference)
#include <cuda_runtime.h>

// ---------------------------------------------------------------------------
// MLPP: b=4, h=w=d=32, c=256, L=16, g=16, lc=16.
// Every op is a 256x256 GEMM over 131072 rows with a gather pattern
//   A(r,k) = X[ rowBase(r) + (k>>4)*s1 + (k&15)*s0 ]
// and an identical scatter pattern for the output. rowBase is a 5-digit
// mixed-radix decode of the row index.
// ---------------------------------------------------------------------------

#define N_ELEMS 33554432  // 4*32*32*32*256

__device__ float g_bufA[N_ELEMS];
__device__ float g_bufB[N_ELEMS];
__device__ float g_bufC[N_ELEMS];

struct GDesc {
    int radix[5];    // slowest..fastest row digits
    int rstride[5];  // element strides per digit
    int s1, s0;      // k-strides: k = (k>>4)*s1 + (k&15)*s0
};

constexpr int BM = 64;
constexpr int BN = 256;
constexpr int BK = 32;
constexpr int TM = 8;
constexpr int TN = 8;
constexpr int NTHREADS = 256;
constexpr int NBLOCKS = 131072 / BM;  // 2048

// AMODE: 0 = a = X[addr] ; 1 = a = (1 + X[addr]) * X2[addr]   (the (1+att)*s fusion)
// EMODE: 0 = OUT = acc + bias ; 1 = OUT += acc + bias ; 2 = OUT = res + acc + bias
// LOADMAP: 0 = consecutive threads walk k (good when s0==1) ;
//          1 = consecutive threads walk rows (good for attn: rows are contiguous c)
template<int AMODE, int EMODE, int LOADMAP>
__global__ __launch_bounds__(NTHREADS, 2)
void ggemm(const float* __restrict__ X,
           const float* __restrict__ X2,
           const float* __restrict__ W,     // [256,256] row-major (k-major)
           const float* __restrict__ bias,  // [256]
           const float* __restrict__ res,
           float* __restrict__ OUT,
           GDesc d)
{
    __shared__ float As[BM * (BK + 1)];   // [row][k], stride 33 (conflict-free both ways)
    __shared__ float Ws[BK][BN];
    __shared__ int   rowAddr[BM];

    const int tid = threadIdx.x;

    // Decode base addresses for this block's 64 rows.
    if (tid < BM) {
        int r = blockIdx.x * BM + tid;
        int base = 0;
        #pragma unroll
        for (int i = 4; i >= 0; --i) {
            int dg = r % d.radix[i];
            r /= d.radix[i];
            base += dg * d.rstride[i];
        }
        rowAddr[tid] = base;
    }
    __syncthreads();

    float acc[TM][TN];
    #pragma unroll
    for (int i = 0; i < TM; ++i)
        #pragma unroll
        for (int j = 0; j < TN; ++j) acc[i][j] = 0.0f;

    const int rg = tid >> 5;   // 0..7  -> rows rg*8 .. rg*8+7
    const int cg = tid & 31;   // 0..31 -> cols cg*8 .. cg*8+7

    for (int kc = 0; kc < 256; kc += BK) {
        // ---- load W chunk [BK][BN], fully coalesced float4 ----
        #pragma unroll
        for (int i = 0; i < 8; ++i) {
            int idx4 = tid + i * NTHREADS;          // 0..2047
            int k  = idx4 >> 6;                      // 0..31
            int c4 = idx4 & 63;                      // 0..63
            float4 v = *reinterpret_cast<const float4*>(W + (kc + k) * 256 + c4 * 4);
            *reinterpret_cast<float4*>(&Ws[k][c4 * 4]) = v;
        }
        // ---- load A chunk [BM][BK] via gather ----
        #pragma unroll
        for (int i = 0; i < 8; ++i) {
            int idx = tid + i * NTHREADS;            // 0..2047
            int row, k;
            if (LOADMAP == 0) { k = idx & 31; row = idx >> 5; }
            else              { row = idx & 63; k = idx >> 6; }
            int kk   = kc + k;
            int addr = rowAddr[row] + (kk >> 4) * d.s1 + (kk & 15) * d.s0;
            float a;
            if (AMODE == 0) a = X[addr];
            else            a = (1.0f + X[addr]) * X2[addr];
            As[row * (BK + 1) + k] = a;
        }
        __syncthreads();

        // ---- FFMA core: 8x8 register tile ----
        #pragma unroll
        for (int k = 0; k < BK; ++k) {
            float a[TM];
            #pragma unroll
            for (int i = 0; i < TM; ++i)
                a[i] = As[(rg * TM + i) * (BK + 1) + k];
            float4 w0 = *reinterpret_cast<const float4*>(&Ws[k][cg * 8]);
            float4 w1 = *reinterpret_cast<const float4*>(&Ws[k][cg * 8 + 4]);
            float wv[TN] = {w0.x, w0.y, w0.z, w0.w, w1.x, w1.y, w1.z, w1.w};
            #pragma unroll
            for (int i = 0; i < TM; ++i)
                #pragma unroll
                for (int j = 0; j < TN; ++j)
                    acc[i][j] += a[i] * wv[j];
        }
        __syncthreads();
    }

    // ---- epilogue: bias (+ accumulate / residual), scatter with (s1,s0) ----
    const int col0 = cg * 8;
    float bj[TN];
    #pragma unroll
    for (int j = 0; j < TN; ++j) bj[j] = bias[col0 + j];

    #pragma unroll
    for (int i = 0; i < TM; ++i) {
        int base = rowAddr[rg * TM + i];
        if (d.s0 == 1) {
            // 8 output cols are contiguous (col>>4 constant across an 8-block)
            int addr = base + (col0 >> 4) * d.s1 + (col0 & 15);
            #pragma unroll
            for (int j = 0; j < TN; ++j) {
                float v = acc[i][j] + bj[j];
                if (EMODE == 1) v += OUT[addr + j];
                if (EMODE == 2) v += res[addr + j];
                OUT[addr + j] = v;
            }
        } else {
            #pragma unroll
            for (int j = 0; j < TN; ++j) {
                int col  = col0 + j;
                int addr = base + (col >> 4) * d.s1 + (col & 15) * d.s0;
                float v = acc[i][j] + bj[j];
                if (EMODE == 1) v += OUT[addr];
                if (EMODE == 2) v += res[addr];
                OUT[addr] = v;
            }
        }
    }
}

extern "C" void kernel_launch(void* const* d_in, const int* in_sizes, int n_in,
                              void* d_out, int out_size)
{
    (void)in_sizes; (void)n_in; (void)out_size;

    const float* x      = (const float*)d_in[0];
    const float* W_h    = (const float*)d_in[1];
    const float* b_h    = (const float*)d_in[2];
    const float* W_w    = (const float*)d_in[3];
    const float* b_w    = (const float*)d_in[4];
    const float* W_c    = (const float*)d_in[5];
    const float* b_c    = (const float*)d_in[6];
    const float* W_d    = (const float*)d_in[7];
    const float* b_d    = (const float*)d_in[8];
    const float* W_attn = (const float*)d_in[9];
    const float* b_attn = (const float*)d_in[10];
    const float* W_1    = (const float*)d_in[11];
    const float* b_1    = (const float*)d_in[12];
    const float* W_2    = (const float*)d_in[13];
    const float* b_2    = (const float*)d_in[14];
    const float* W_3    = (const float*)d_in[15];
    const float* b_3    = (const float*)d_in[16];
    float* out = (float*)d_out;

    float *bufA, *bufB, *bufC;
    cudaGetSymbolAddress((void**)&bufA, g_bufA);
    cudaGetSymbolAddress((void**)&bufB, g_bufB);
    cudaGetSymbolAddress((void**)&bufC, g_bufC);

    // x strides (elements): c=1, d=256, w=8192, h=262144, b=8388608
    // attn:  rows (b,h1,w1,d,c),  k=(lh,lw)
    GDesc d_att  = {{4, 2, 2, 32, 256}, {8388608, 4194304, 131072, 256, 1}, 262144, 8192};
    // plain channel GEMM: rows (b,h,w,d), k=c
    GDesc d_cont = {{1, 4, 32, 32, 32}, {0, 8388608, 262144, 8192, 256}, 16, 1};
    // x_h: rows (b,h1,w,d,lc), k=(lh,g)
    GDesc d_h    = {{4, 2, 32, 32, 16}, {8388608, 4194304, 8192, 256, 16}, 262144, 1};
    // x_w: rows (b,h,w1,d,lc), k=(lw,g)
    GDesc d_w    = {{4, 32, 2, 32, 16}, {8388608, 262144, 131072, 256, 16}, 8192, 1};
    // x_d: rows (b,h,w,d1,l), k=(ld,g)
    GDesc d_d    = {{4, 32, 32, 2, 16}, {8388608, 262144, 8192, 4096, 16}, 256, 1};

    dim3 grid(NBLOCKS), block(NTHREADS);

    // Stage A (ip_mlp):
    // 1) t_att = attn(x)                         -> bufA
    ggemm<0, 0, 1><<<grid, block>>>(x, nullptr, W_attn, b_attn, nullptr, bufA, d_att);
    // 2) t_s = x @ W_c + b_c                     -> bufB
    ggemm<0, 0, 0><<<grid, block>>>(x, nullptr, W_c, b_c, nullptr, bufB, d_cont);
    // 3) t_s += x_h                              -> bufB
    ggemm<0, 1, 0><<<grid, block>>>(x, nullptr, W_h, b_h, nullptr, bufB, d_h);
    // 4) t_s += x_w                              -> bufB
    ggemm<0, 1, 0><<<grid, block>>>(x, nullptr, W_w, b_w, nullptr, bufB, d_w);
    // 5) x1 = x + ((1+t_att)*t_s) @ W_1 + b_1    -> bufC   (A-load fusion)
    ggemm<1, 2, 0><<<grid, block>>>(bufA, bufB, W_1, b_1, x, bufC, d_cont);

    // Stage B (tp_mlp):
    // 6) t_d = dgather(x1) @ W_d + b_d           -> bufA
    ggemm<0, 0, 0><<<grid, block>>>(bufC, nullptr, W_d, b_d, nullptr, bufA, d_d);
    // 7) x2 = x1 + t_d @ W_2 + b_2               -> bufB
    ggemm<0, 2, 0><<<grid, block>>>(bufA, nullptr, W_2, b_2, bufC, bufB, d_cont);

    // Stage C:
    // 8) out = x2 + x2 @ W_3 + b_3               -> d_out
    ggemm<0, 2, 0><<<grid, block>>>(bufB, nullptr, W_3, b_3, bufB, out, d_cont);
}

// round 6
// speedup vs baseline: 3.0547x; 3.0547x over previous
#include <cuda_runtime.h>
#include <cstdint>

// ---------------------------------------------------------------------------
// MLPP on tensor cores (mma.sync m16n8k8 tf32).
// Every op is a 256x256 GEMM over 131072 rows with a gather/scatter pattern
//   addr(r,k) = rowBase(r) + (k>>4)*s1 + (k&15)*s0
// rowBase is a 5-digit mixed-radix decode of the row index.
// ---------------------------------------------------------------------------

#define N_ELEMS 33554432  // 4*32*32*32*256

__device__ float g_bufA[N_ELEMS];
__device__ float g_bufB[N_ELEMS];
__device__ float g_bufC[N_ELEMS];
__device__ float g_Wp[8][65536];   // fragment-permuted, tf32-rounded weights

struct GDesc {
    int radix[5];    // slowest..fastest row digits
    int rstride[5];  // element strides per digit
    int s1, s0;      // k strides
};

__device__ __forceinline__ uint32_t f2tf32(float f) {
    uint32_t r;
    asm("cvt.rna.tf32.f32 %0, %1;" : "=r"(r) : "f"(f));
    return r;
}

__device__ __forceinline__ void mma_tf32(float* c, const uint32_t* a,
                                         uint32_t b0, uint32_t b1) {
    asm volatile(
        "mma.sync.aligned.m16n8k8.row.col.f32.tf32.tf32.f32 "
        "{%0,%1,%2,%3}, {%4,%5,%6,%7}, {%8,%9}, {%0,%1,%2,%3};\n"
        : "+f"(c[0]), "+f"(c[1]), "+f"(c[2]), "+f"(c[3])
        : "r"(a[0]), "r"(a[1]), "r"(a[2]), "r"(a[3]), "r"(b0), "r"(b1));
}

__device__ __forceinline__ void cpasync16(uint32_t saddr, const void* gaddr) {
    asm volatile("cp.async.cg.shared.global [%0], [%1], 16;\n"
                 :: "r"(saddr), "l"(gaddr) : "memory");
}
__device__ __forceinline__ void cp_commit() {
    asm volatile("cp.async.commit_group;\n" ::: "memory");
}

// ---- Weight permute pre-kernel: Wp[(k>>4)*256 + n][perm(k&15)] = tf32(W[k][n])
__global__ void permW8(const float* w0, const float* w1, const float* w2, const float* w3,
                       const float* w4, const float* w5, const float* w6, const float* w7)
{
    const float* ws[8] = {w0, w1, w2, w3, w4, w5, w6, w7};
    int wi = blockIdx.y;
    int k  = blockIdx.x;          // 0..255
    int n  = threadIdx.x;         // 0..255
    float v = ws[wi][k * 256 + n];
    int kl = k & 15;
    int p  = ((kl & 3) << 2) | (kl >> 2);
    g_Wp[wi][(((k >> 4) * 256) + n) * 16 + p] = __uint_as_float(f2tf32(v));
}

// ---------------------------------------------------------------------------
// Tensor-core GEMM: 131072 x 256 x 256, BM=128 BN=128 BK=32, 8 warps (4Mx2N).
// AMODE: 0: a = X[addr] ; 1: a = (1+X[addr])*X2[addr]
// EMODE: 0: OUT = acc+bias ; 1: OUT += acc+bias ; 2: OUT = res+acc+bias
// GATHER: 0: s0==1 (float4 gather) ; 1: scalar gather (attn), rows contiguous
// ---------------------------------------------------------------------------
template<int AMODE, int EMODE, int GATHER>
__global__ __launch_bounds__(256, 2)
void tgemm(const float* __restrict__ X, const float* __restrict__ X2,
           const float* __restrict__ Wp, const float* __restrict__ bias,
           const float* __restrict__ res, float* __restrict__ OUT, GDesc d)
{
    constexpr int ASTR = (GATHER == 0) ? 20 : 17;     // A smem row stride (floats)
    constexpr int AFL  = 2 * 128 * ASTR;              // A floats per stage (2 k16 groups)
    constexpr int WFL  = 2 * 2048;                    // W floats per stage
    constexpr int STG  = AFL + WFL;                   // floats per stage

    extern __shared__ float sm[];
    __shared__ int rowAddr[128];

    const int tid = threadIdx.x;
    const int nb  = blockIdx.x;   // N-block: 0 / 1

    if (tid < 128) {
        int r = blockIdx.y * 128 + tid;
        int base = 0;
        #pragma unroll
        for (int i = 4; i >= 0; --i) {
            int dg = r % d.radix[i]; r /= d.radix[i];
            base += dg * d.rstride[i];
        }
        rowAddr[tid] = base;
    }
    __syncthreads();

    const int wid   = tid >> 5, lane = tid & 31;
    const int warpM = wid & 3,  warpN = wid >> 2;
    const int g     = lane >> 2, q    = lane & 3;

    float acc[2][8][4];
    #pragma unroll
    for (int mi = 0; mi < 2; ++mi)
        #pragma unroll
        for (int ni = 0; ni < 8; ++ni)
            #pragma unroll
            for (int j = 0; j < 4; ++j) acc[mi][ni][j] = 0.0f;

    // A prefetch registers
    float4 av4[4];     // GATHER==0
    float  avs[16];    // GATHER==1

    // ---- helpers as lambdas ----
    auto ldA = [&](int ko) {
        if (GATHER == 0) {
            #pragma unroll
            for (int i = 0; i < 4; ++i) {
                int idx4 = tid + i * 256;               // 0..1023
                int row = idx4 >> 3, j = idx4 & 7;
                int kg = j >> 2, jj = j & 3;
                int ga = rowAddr[row] + (2 * ko + kg) * d.s1 + 4 * jj;  // s0==1
                float4 v = *reinterpret_cast<const float4*>(X + ga);
                if (AMODE == 1) {
                    float4 v2 = *reinterpret_cast<const float4*>(X2 + ga);
                    v.x = (1.0f + v.x) * v2.x;  v.y = (1.0f + v.y) * v2.y;
                    v.z = (1.0f + v.z) * v2.z;  v.w = (1.0f + v.w) * v2.w;
                }
                av4[i] = v;
            }
        } else {
            #pragma unroll
            for (int i = 0; i < 16; ++i) {
                int idx = tid + i * 256;                // 0..4095
                int row = idx & 127, ks = idx >> 7;     // rows contiguous in gmem
                int ga = rowAddr[row] + (2 * ko + (ks >> 4)) * d.s1 + (ks & 15) * d.s0;
                avs[i] = X[ga];
            }
        }
    };

    auto stsA = [&](int stage) {
        float* ab = sm + stage * STG;
        if (GATHER == 0) {
            #pragma unroll
            for (int i = 0; i < 4; ++i) {
                int idx4 = tid + i * 256;
                int row = idx4 >> 3, j = idx4 & 7;
                int kg = j >> 2, jj = j & 3;
                uint4 u;
                u.x = f2tf32(av4[i].x); u.y = f2tf32(av4[i].y);
                u.z = f2tf32(av4[i].z); u.w = f2tf32(av4[i].w);
                *reinterpret_cast<uint4*>(ab + kg * 128 * ASTR + row * ASTR + 4 * jj) = u;
            }
        } else {
            #pragma unroll
            for (int i = 0; i < 16; ++i) {
                int idx = tid + i * 256;
                int row = idx & 127, ks = idx >> 7;
                ab[(ks >> 4) * 128 * ASTR + row * ASTR + (ks & 15)] =
                    __uint_as_float(f2tf32(avs[i]));
            }
        }
    };

    auto cpW = [&](int ko, int stage) {
        float* wb = sm + stage * STG + AFL;
        #pragma unroll
        for (int i = 0; i < 4; ++i) {
            int idx4 = tid + i * 256;                   // 0..1023
            int kg  = idx4 >> 9;
            int off = idx4 & 511;                       // float4 index within 8KB chunk
            const float* src = Wp + ((2 * ko + kg) * 256 + nb * 128) * 16 + off * 4;
            uint32_t dst = (uint32_t)__cvta_generic_to_shared(wb + kg * 2048 + off * 4);
            cpasync16(dst, src);
        }
    };

    auto compute = [&](int stage) {
        const float* ab = sm + stage * STG;
        const float* wb = ab + AFL;
        #pragma unroll
        for (int kg = 0; kg < 2; ++kg) {
            const float* A0 = ab + kg * 128 * ASTR;
            uint32_t af[2][2][4];
            #pragma unroll
            for (int mi = 0; mi < 2; ++mi) {
                const float* pr0 = A0 + (warpM * 32 + mi * 16 + g) * ASTR;
                const float* pr1 = pr0 + 8 * ASTR;
                #pragma unroll
                for (int kh = 0; kh < 2; ++kh) {
                    af[mi][kh][0] = __float_as_uint(pr0[q + 8 * kh]);
                    af[mi][kh][1] = __float_as_uint(pr1[q + 8 * kh]);
                    af[mi][kh][2] = __float_as_uint(pr0[q + 4 + 8 * kh]);
                    af[mi][kh][3] = __float_as_uint(pr1[q + 4 + 8 * kh]);
                }
            }
            const float* W0 = wb + kg * 2048 + (warpN * 64) * 16 + 4 * q;
            #pragma unroll
            for (int ni = 0; ni < 8; ++ni) {
                float4 bv = *reinterpret_cast<const float4*>(W0 + (ni * 8 + g) * 16);
                uint32_t b0 = __float_as_uint(bv.x), b1 = __float_as_uint(bv.y);
                uint32_t b2 = __float_as_uint(bv.z), b3 = __float_as_uint(bv.w);
                #pragma unroll
                for (int mi = 0; mi < 2; ++mi) {
                    mma_tf32(acc[mi][ni], af[mi][0], b0, b1);
                    mma_tf32(acc[mi][ni], af[mi][1], b2, b3);
                }
            }
        }
    };

    // ---- pipelined main loop: 8 stages of k32, double-buffered ----
    ldA(0);
    cpW(0, 0); cp_commit();

    #pragma unroll
    for (int ko = 0; ko < 8; ++ko) {
        int cur = ko & 1;
        if (ko < 7) { cpW(ko + 1, cur ^ 1); cp_commit(); }
        if (ko < 7) asm volatile("cp.async.wait_group 1;\n" ::: "memory");
        else        asm volatile("cp.async.wait_group 0;\n" ::: "memory");
        stsA(cur);
        __syncthreads();
        if (ko < 7) ldA(ko + 1);
        compute(cur);
        __syncthreads();
    }

    // ---- epilogue: bias (+accumulate / +residual), scatter ----
    #pragma unroll
    for (int mi = 0; mi < 2; ++mi) {
        #pragma unroll
        for (int h = 0; h < 2; ++h) {
            int row  = warpM * 32 + mi * 16 + 8 * h + g;
            int base = rowAddr[row];
            #pragma unroll
            for (int ni = 0; ni < 8; ++ni) {
                int col = nb * 128 + warpN * 64 + ni * 8 + 2 * q;   // even, pair in-group
                int a0  = base + (col >> 4) * d.s1 + (col & 15) * d.s0;
                int a1  = a0 + d.s0;
                float v0 = acc[mi][ni][2 * h + 0] + bias[col];
                float v1 = acc[mi][ni][2 * h + 1] + bias[col + 1];
                if (EMODE == 1) { v0 += OUT[a0]; v1 += OUT[a1]; }
                if (EMODE == 2) { v0 += res[a0]; v1 += res[a1]; }
                OUT[a0] = v0; OUT[a1] = v1;
            }
        }
    }
}

// ---------------------------------------------------------------------------

extern "C" void kernel_launch(void* const* d_in, const int* in_sizes, int n_in,
                              void* d_out, int out_size)
{
    (void)in_sizes; (void)n_in; (void)out_size;

    const float* x      = (const float*)d_in[0];
    const float* W_h    = (const float*)d_in[1];
    const float* b_h    = (const float*)d_in[2];
    const float* W_w    = (const float*)d_in[3];
    const float* b_w    = (const float*)d_in[4];
    const float* W_c    = (const float*)d_in[5];
    const float* b_c    = (const float*)d_in[6];
    const float* W_d    = (const float*)d_in[7];
    const float* b_d    = (const float*)d_in[8];
    const float* W_attn = (const float*)d_in[9];
    const float* b_attn = (const float*)d_in[10];
    const float* W_1    = (const float*)d_in[11];
    const float* b_1    = (const float*)d_in[12];
    const float* W_2    = (const float*)d_in[13];
    const float* b_2    = (const float*)d_in[14];
    const float* W_3    = (const float*)d_in[15];
    const float* b_3    = (const float*)d_in[16];
    float* out = (float*)d_out;

    float *bufA, *bufB, *bufC, *wp;
    cudaGetSymbolAddress((void**)&bufA, g_bufA);
    cudaGetSymbolAddress((void**)&bufB, g_bufB);
    cudaGetSymbolAddress((void**)&bufC, g_bufC);
    cudaGetSymbolAddress((void**)&wp,   g_Wp);
    const float* Wp0 = wp;                 // W_h
    const float* Wp1 = wp + 1 * 65536;     // W_w
    const float* Wp2 = wp + 2 * 65536;     // W_c
    const float* Wp3 = wp + 3 * 65536;     // W_d
    const float* Wp4 = wp + 4 * 65536;     // W_attn
    const float* Wp5 = wp + 5 * 65536;     // W_1
    const float* Wp6 = wp + 6 * 65536;     // W_2
    const float* Wp7 = wp + 7 * 65536;     // W_3

    // opt-in smem sizes (idempotent; harmless during capture)
    constexpr int SM_G0 = 2 * (2 * 128 * 20 + 4096) * 4;   // 73728 B
    constexpr int SM_G1 = 2 * (2 * 128 * 17 + 4096) * 4;   // 67584 B
    cudaFuncSetAttribute(tgemm<0,0,1>, cudaFuncAttributeMaxDynamicSharedMemorySize, SM_G1);
    cudaFuncSetAttribute(tgemm<0,0,0>, cudaFuncAttributeMaxDynamicSharedMemorySize, SM_G0);
    cudaFuncSetAttribute(tgemm<0,1,0>, cudaFuncAttributeMaxDynamicSharedMemorySize, SM_G0);
    cudaFuncSetAttribute(tgemm<1,2,0>, cudaFuncAttributeMaxDynamicSharedMemorySize, SM_G0);
    cudaFuncSetAttribute(tgemm<0,2,0>, cudaFuncAttributeMaxDynamicSharedMemorySize, SM_G0);

    // x strides (elements): c=1, d=256, w=8192, h=262144, b=8388608
    GDesc d_att  = {{4, 2, 2, 32, 256}, {8388608, 4194304, 131072, 256, 1}, 262144, 8192};
    GDesc d_cont = {{1, 4, 32, 32, 32}, {0, 8388608, 262144, 8192, 256}, 16, 1};
    GDesc d_h    = {{4, 2, 32, 32, 16}, {8388608, 4194304, 8192, 256, 16}, 262144, 1};
    GDesc d_w    = {{4, 32, 2, 32, 16}, {8388608, 262144, 131072, 256, 16}, 8192, 1};
    GDesc d_d    = {{4, 32, 32, 2, 16}, {8388608, 262144, 8192, 4096, 16}, 256, 1};

    // permute + tf32-round all 8 weight matrices (2 MB; trivial)
    permW8<<<dim3(256, 8), 256>>>(W_h, W_w, W_c, W_d, W_attn, W_1, W_2, W_3);

    dim3 grid(2, 1024), block(256);

    // Stage A (ip_mlp):
    tgemm<0,0,1><<<grid, block, SM_G1>>>(x,    nullptr, Wp4, b_attn, nullptr, bufA, d_att);
    tgemm<0,0,0><<<grid, block, SM_G0>>>(x,    nullptr, Wp2, b_c,    nullptr, bufB, d_cont);
    tgemm<0,1,0><<<grid, block, SM_G0>>>(x,    nullptr, Wp0, b_h,    nullptr, bufB, d_h);
    tgemm<0,1,0><<<grid, block, SM_G0>>>(x,    nullptr, Wp1, b_w,    nullptr, bufB, d_w);
    tgemm<1,2,0><<<grid, block, SM_G0>>>(bufA, bufB,    Wp5, b_1,    x,       bufC, d_cont);
    // Stage B (tp_mlp):
    tgemm<0,0,0><<<grid, block, SM_G0>>>(bufC, nullptr, Wp3, b_d,    nullptr, bufA, d_d);
    tgemm<0,2,0><<<grid, block, SM_G0>>>(bufA, nullptr, Wp6, b_2,    bufC,    bufB, d_cont);
    // Stage C:
    tgemm<0,2,0><<<grid, block, SM_G0>>>(bufB, nullptr, Wp7, b_3,    bufB,    out,  d_cont);
}

// round 8
// speedup vs baseline: 3.5167x; 1.1512x over previous
#include <cuda_runtime.h>
#include <cstdint>

// ---------------------------------------------------------------------------
// MLPP on mma.sync m16n8k8 tf32 (sm_100 legacy tensor path — tcgen05 is not
// available under the harness's -arch=sm_100 compile target).
// Every op is a 256x256 GEMM over 131072 rows with gather pattern
//   addr(r,k) = rowBase(r) + (k>>4)*s1 + (k&15)*s0
// and identical scatter for the output.
// This round: fully asynchronous operand feed (cp.async for both A-gather and
// W), 3-stage pipeline, one barrier per k32 stage. A enters the mma as raw
// fp32 bits (HW truncates to tf32); W is RNA-rounded in a prep kernel.
// ---------------------------------------------------------------------------

#define N_ELEMS 33554432  // 4*32*32*32*256

__device__ float g_bufA[N_ELEMS];
__device__ float g_bufB[N_ELEMS];
__device__ float g_bufC[N_ELEMS];
__device__ float g_Wp[8][65536];   // fragment-permuted, tf32(RNA) weights

struct GDesc {
    int radix[5];    // slowest..fastest row digits
    int rstride[5];  // element strides per digit
    int s1, s0;      // k strides
};

__device__ __forceinline__ uint32_t f2tf32(float f) {
    uint32_t r; asm("cvt.rna.tf32.f32 %0, %1;" : "=r"(r) : "f"(f)); return r;
}
__device__ __forceinline__ uint32_t smem_u32(const void* p) {
    return (uint32_t)__cvta_generic_to_shared(p);
}
__device__ __forceinline__ void mma_tf32(float* c, const uint32_t* a,
                                         uint32_t b0, uint32_t b1) {
    asm volatile(
        "mma.sync.aligned.m16n8k8.row.col.f32.tf32.tf32.f32 "
        "{%0,%1,%2,%3}, {%4,%5,%6,%7}, {%8,%9}, {%0,%1,%2,%3};\n"
        : "+f"(c[0]), "+f"(c[1]), "+f"(c[2]), "+f"(c[3])
        : "r"(a[0]), "r"(a[1]), "r"(a[2]), "r"(a[3]), "r"(b0), "r"(b1));
}
__device__ __forceinline__ void cp16(uint32_t dst, const void* src) {
    asm volatile("cp.async.cg.shared.global [%0], [%1], 16;\n"
                 :: "r"(dst), "l"(src) : "memory");
}
__device__ __forceinline__ void cp4(uint32_t dst, const void* src) {
    asm volatile("cp.async.ca.shared.global [%0], [%1], 4;\n"
                 :: "r"(dst), "l"(src) : "memory");
}
__device__ __forceinline__ void cp_commit() {
    asm volatile("cp.async.commit_group;\n" ::: "memory");
}

// ---- Weight permute pre-kernel: Wp[(k>>4)*256 + n][perm(k&15)] = tf32(W[k][n])
__global__ void permW8(const float* w0, const float* w1, const float* w2, const float* w3,
                       const float* w4, const float* w5, const float* w6, const float* w7)
{
    const float* ws[8] = {w0, w1, w2, w3, w4, w5, w6, w7};
    int wi = blockIdx.y;
    int k  = blockIdx.x;          // 0..255
    int n  = threadIdx.x;         // 0..255
    float v = ws[wi][k * 256 + n];
    int kl = k & 15;
    int p  = ((kl & 3) << 2) | (kl >> 2);
    g_Wp[wi][(((k >> 4) * 256) + n) * 16 + p] = __uint_as_float(f2tf32(v));
}

// ---------------------------------------------------------------------------
// BM=128 BN=128 BK=32, 8 warps (4Mx2N, warp tile 32x64), 3-stage cp.async.
// AMODE: 0: a = X[addr] (async) ; 1: a = (1+X[addr])*X2[addr] (register-staged)
// EMODE: 0: OUT = acc+bias ; 1: OUT += acc+bias ; 2: OUT = res+acc+bias
// GATHER: 0: s0==1 (cp.async 16B) ; 1: scalar gather / attn (cp.async 4B)
// ---------------------------------------------------------------------------
template<int AMODE, int EMODE, int GATHER>
__global__ __launch_bounds__(256, 2)
void tgemm(const float* __restrict__ X, const float* __restrict__ X2,
           const float* __restrict__ Wp, const float* __restrict__ bias,
           const float* __restrict__ res, float* __restrict__ OUT, GDesc d)
{
    constexpr int ASTR  = 20;                 // A smem row stride (floats)
    constexpr int AFL   = 2 * 128 * ASTR;     // 5120 floats / stage
    constexpr int WFL   = 4096;               // 4096 floats / stage
    constexpr int STG_F = AFL + WFL;          // 9216 floats / stage
    extern __shared__ float sm[];
    __shared__ int rowAddr[128];

    const int tid = threadIdx.x;
    const int nb  = blockIdx.x;               // N-block: 0 / 1

    if (tid < 128) {
        int r = blockIdx.y * 128 + tid;
        int base = 0;
        #pragma unroll
        for (int i = 4; i >= 0; --i) {
            int dg = r % d.radix[i]; r /= d.radix[i];
            base += dg * d.rstride[i];
        }
        rowAddr[tid] = base;
    }
    __syncthreads();

    // Cache this thread's gather row bases in registers (row ids are s-invariant).
    int ra4[4];   // GATHER==0 / AMODE==1
    int ra16[16]; // GATHER==1
    if (GATHER == 0) {
        #pragma unroll
        for (int i = 0; i < 4; ++i) ra4[i] = rowAddr[(tid + i * 256) >> 3];
    } else {
        #pragma unroll
        for (int i = 0; i < 16; ++i) ra16[i] = rowAddr[(tid + i * 256) & 127];
    }

    const int wid   = tid >> 5, lane = tid & 31;
    const int warpM = wid & 3,  warpN = wid >> 2;
    const int g     = lane >> 2, q    = lane & 3;

    float acc[2][8][4];
    #pragma unroll
    for (int mi = 0; mi < 2; ++mi)
        #pragma unroll
        for (int ni = 0; ni < 8; ++ni)
            #pragma unroll
            for (int j = 0; j < 4; ++j) acc[mi][ni][j] = 0.0f;

    // ---- stage issue: A (async or register-staged) + W (async) ----
    auto issueA = [&](int s, int p) {
        float* ab = sm + p * STG_F;
        if (AMODE == 0) {
            if (GATHER == 0) {
                #pragma unroll
                for (int i = 0; i < 4; ++i) {
                    int idx = tid + i * 256;              // 0..1023
                    int row = idx >> 3, rem = idx & 7;
                    int kg = rem >> 2, j = rem & 3;
                    const float* src = X + ra4[i] + (2 * s + kg) * d.s1 + 4 * j;
                    cp16(smem_u32(ab + kg * (128 * ASTR) + row * ASTR + 4 * j), src);
                }
            } else {
                #pragma unroll
                for (int i = 0; i < 16; ++i) {
                    int idx = tid + i * 256;              // 0..4095
                    int row = idx & 127, k = idx >> 7;    // rows contiguous in gmem
                    const float* src = X + ra16[i] + (2 * s + (k >> 4)) * d.s1
                                         + (k & 15) * d.s0;
                    cp4(smem_u32(ab + (k >> 4) * (128 * ASTR) + row * ASTR + (k & 15)), src);
                }
            }
        } else {
            #pragma unroll
            for (int i = 0; i < 4; ++i) {
                int idx = tid + i * 256;
                int row = idx >> 3, rem = idx & 7;
                int kg = rem >> 2, j = rem & 3;
                int ga = ra4[i] + (2 * s + kg) * d.s1 + 4 * j;
                float4 v  = *reinterpret_cast<const float4*>(X + ga);
                float4 v2 = *reinterpret_cast<const float4*>(X2 + ga);
                v.x = (1.0f + v.x) * v2.x;  v.y = (1.0f + v.y) * v2.y;
                v.z = (1.0f + v.z) * v2.z;  v.w = (1.0f + v.w) * v2.w;
                *reinterpret_cast<float4*>(ab + kg * (128 * ASTR) + row * ASTR + 4 * j) = v;
            }
        }
    };

    auto issueW = [&](int s, int p) {
        float* wb = sm + p * STG_F + AFL;
        #pragma unroll
        for (int i = 0; i < 4; ++i) {
            int idx4 = tid + i * 256;                     // 0..1023
            int kg = idx4 >> 9, off = idx4 & 511;
            const float* src = Wp + ((2 * s + kg) * 256 + nb * 128) * 16 + off * 4;
            cp16(smem_u32(wb + kg * 2048 + off * 4), src);
        }
    };

    auto compute = [&](int p) {
        const float* ab = sm + p * STG_F;
        const float* wb = ab + AFL;
        #pragma unroll
        for (int kg = 0; kg < 2; ++kg) {
            const float* A0 = ab + kg * (128 * ASTR);
            uint32_t af[2][2][4];
            #pragma unroll
            for (int mi = 0; mi < 2; ++mi) {
                const float* pr0 = A0 + (warpM * 32 + mi * 16 + g) * ASTR;
                const float* pr1 = pr0 + 8 * ASTR;
                #pragma unroll
                for (int kh = 0; kh < 2; ++kh) {
                    af[mi][kh][0] = __float_as_uint(pr0[q + 8 * kh]);
                    af[mi][kh][1] = __float_as_uint(pr1[q + 8 * kh]);
                    af[mi][kh][2] = __float_as_uint(pr0[q + 4 + 8 * kh]);
                    af[mi][kh][3] = __float_as_uint(pr1[q + 4 + 8 * kh]);
                }
            }
            const float* W0 = wb + kg * 2048 + (warpN * 64) * 16 + 4 * q;
            #pragma unroll
            for (int ni = 0; ni < 8; ++ni) {
                float4 bv = *reinterpret_cast<const float4*>(W0 + (ni * 8 + g) * 16);
                uint32_t b0 = __float_as_uint(bv.x), b1 = __float_as_uint(bv.y);
                uint32_t b2 = __float_as_uint(bv.z), b3 = __float_as_uint(bv.w);
                #pragma unroll
                for (int mi = 0; mi < 2; ++mi) {
                    mma_tf32(acc[mi][ni], af[mi][0], b0, b1);
                    mma_tf32(acc[mi][ni], af[mi][1], b2, b3);
                }
            }
        }
    };

    // ---- 3-stage pipeline over 8 k32 stages ----
    issueA(0, 0); issueW(0, 0); cp_commit();
    issueA(1, 1); issueW(1, 1); cp_commit();

    #pragma unroll 1
    for (int s = 0; s < 8; ++s) {
        if (s < 7) asm volatile("cp.async.wait_group 1;\n" ::: "memory");
        else       asm volatile("cp.async.wait_group 0;\n" ::: "memory");
        __syncthreads();
        if (s < 6) { issueA(s + 2, (s + 2) % 3); issueW(s + 2, (s + 2) % 3); cp_commit(); }
        compute(s % 3);
    }

    // ---- epilogue: bias (+accumulate / +residual), scatter ----
    #pragma unroll
    for (int mi = 0; mi < 2; ++mi) {
        #pragma unroll
        for (int h = 0; h < 2; ++h) {
            int row  = warpM * 32 + mi * 16 + 8 * h + g;
            int base = rowAddr[row];
            #pragma unroll
            for (int ni = 0; ni < 8; ++ni) {
                int col = nb * 128 + warpN * 64 + ni * 8 + 2 * q;
                int a0  = base + (col >> 4) * d.s1 + (col & 15) * d.s0;
                int a1  = a0 + d.s0;
                float v0 = acc[mi][ni][2 * h + 0] + bias[col];
                float v1 = acc[mi][ni][2 * h + 1] + bias[col + 1];
                if (EMODE == 1) { v0 += OUT[a0]; v1 += OUT[a1]; }
                if (EMODE == 2) { v0 += res[a0]; v1 += res[a1]; }
                OUT[a0] = v0; OUT[a1] = v1;
            }
        }
    }
}

// ---------------------------------------------------------------------------

extern "C" void kernel_launch(void* const* d_in, const int* in_sizes, int n_in,
                              void* d_out, int out_size)
{
    (void)in_sizes; (void)n_in; (void)out_size;

    const float* x      = (const float*)d_in[0];
    const float* W_h    = (const float*)d_in[1];
    const float* b_h    = (const float*)d_in[2];
    const float* W_w    = (const float*)d_in[3];
    const float* b_w    = (const float*)d_in[4];
    const float* W_c    = (const float*)d_in[5];
    const float* b_c    = (const float*)d_in[6];
    const float* W_d    = (const float*)d_in[7];
    const float* b_d    = (const float*)d_in[8];
    const float* W_attn = (const float*)d_in[9];
    const float* b_attn = (const float*)d_in[10];
    const float* W_1    = (const float*)d_in[11];
    const float* b_1    = (const float*)d_in[12];
    const float* W_2    = (const float*)d_in[13];
    const float* b_2    = (const float*)d_in[14];
    const float* W_3    = (const float*)d_in[15];
    const float* b_3    = (const float*)d_in[16];
    float* out = (float*)d_out;

    float *bufA, *bufB, *bufC, *wp;
    cudaGetSymbolAddress((void**)&bufA, g_bufA);
    cudaGetSymbolAddress((void**)&bufB, g_bufB);
    cudaGetSymbolAddress((void**)&bufC, g_bufC);
    cudaGetSymbolAddress((void**)&wp,   g_Wp);
    const float* Wp_h    = wp + 0 * 65536;
    const float* Wp_w    = wp + 1 * 65536;
    const float* Wp_c    = wp + 2 * 65536;
    const float* Wp_d    = wp + 3 * 65536;
    const float* Wp_attn = wp + 4 * 65536;
    const float* Wp_1    = wp + 5 * 65536;
    const float* Wp_2    = wp + 6 * 65536;
    const float* Wp_3    = wp + 7 * 65536;

    constexpr int SMEM = 3 * 9216 * 4;   // 110592 B (3 stages x 36 KB)
    cudaFuncSetAttribute(tgemm<0,0,1>, cudaFuncAttributeMaxDynamicSharedMemorySize, SMEM);
    cudaFuncSetAttribute(tgemm<0,0,0>, cudaFuncAttributeMaxDynamicSharedMemorySize, SMEM);
    cudaFuncSetAttribute(tgemm<0,1,0>, cudaFuncAttributeMaxDynamicSharedMemorySize, SMEM);
    cudaFuncSetAttribute(tgemm<1,2,0>, cudaFuncAttributeMaxDynamicSharedMemorySize, SMEM);
    cudaFuncSetAttribute(tgemm<0,2,0>, cudaFuncAttributeMaxDynamicSharedMemorySize, SMEM);

    // x strides (elements): c=1, d=256, w=8192, h=262144, b=8388608
    GDesc d_att  = {{4, 2, 2, 32, 256}, {8388608, 4194304, 131072, 256, 1}, 262144, 8192};
    GDesc d_cont = {{1, 4, 32, 32, 32}, {0, 8388608, 262144, 8192, 256}, 16, 1};
    GDesc d_h    = {{4, 2, 32, 32, 16}, {8388608, 4194304, 8192, 256, 16}, 262144, 1};
    GDesc d_w    = {{4, 32, 2, 32, 16}, {8388608, 262144, 131072, 256, 16}, 8192, 1};
    GDesc d_d    = {{4, 32, 32, 2, 16}, {8388608, 262144, 8192, 4096, 16}, 256, 1};

    // permute + tf32(RNA)-round all 8 weight matrices (2 MB; trivial)
    permW8<<<dim3(256, 8), 256>>>(W_h, W_w, W_c, W_d, W_attn, W_1, W_2, W_3);

    dim3 grid(2, 1024), block(256);

    // Stage A (ip_mlp):
    tgemm<0,0,1><<<grid, block, SMEM>>>(x,    nullptr, Wp_attn, b_attn, nullptr, bufA, d_att);
    tgemm<0,0,0><<<grid, block, SMEM>>>(x,    nullptr, Wp_c,    b_c,    nullptr, bufB, d_cont);
    tgemm<0,1,0><<<grid, block, SMEM>>>(x,    nullptr, Wp_h,    b_h,    nullptr, bufB, d_h);
    tgemm<0,1,0><<<grid, block, SMEM>>>(x,    nullptr, Wp_w,    b_w,    nullptr, bufB, d_w);
    tgemm<1,2,0><<<grid, block, SMEM>>>(bufA, bufB,    Wp_1,    b_1,    x,       bufC, d_cont);
    // Stage B (tp_mlp):
    tgemm<0,0,0><<<grid, block, SMEM>>>(bufC, nullptr, Wp_d,    b_d,    nullptr, bufA, d_d);
    tgemm<0,2,0><<<grid, block, SMEM>>>(bufA, nullptr, Wp_2,    b_2,    bufC,    bufB, d_cont);
    // Stage C:
    tgemm<0,2,0><<<grid, block, SMEM>>>(bufB, nullptr, Wp_3,    b_3,    bufB,    out,  d_cont);
}

// round 11
// speedup vs baseline: 3.6227x; 1.0302x over previous
#include <cuda_runtime.h>
#include <cstdint>

// ---------------------------------------------------------------------------
// MLPP on mma.sync m16n8k8 tf32 (sm_100 legacy tensor path; tcgen05 is not
// available under the harness's -arch=sm_100 compile target).
// Every op is a 256x256 GEMM over 131072 rows with gather pattern
//   addr(r,k) = rowBase(r) + (k>>4)*s1 + (k&15)*s0
// and identical scatter for the output. rowBase = 5-digit mixed-radix decode.
// R11 = R10 resubmitted (R10 bench hit infra failure; kernel never ran):
// R8 structure (separate GEMMs; 3-way fusion is mathematically invalid —
// the three gathers use different row/col coordinate systems), plus:
//   - ldmatrix.x4 A-fragment loads (8 LDSM vs 32 scalar LDS per warp-stage)
//   - per-thread pointer-increment addressing (stage stride is constant)
// ---------------------------------------------------------------------------

#define N_ELEMS 33554432  // 4*32*32*32*256

__device__ float g_bufA[N_ELEMS];
__device__ float g_bufB[N_ELEMS];
__device__ float g_bufC[N_ELEMS];
__device__ float g_Wp[8][65536];   // fragment-permuted, tf32(RNA) weights

struct GDesc {
    int radix[5];    // slowest..fastest row digits
    int rstride[5];  // element strides per digit
    int s1, s0;      // k strides
};

__device__ __forceinline__ uint32_t f2tf32(float f) {
    uint32_t r; asm("cvt.rna.tf32.f32 %0, %1;" : "=r"(r) : "f"(f)); return r;
}
__device__ __forceinline__ uint32_t smem_u32(const void* p) {
    return (uint32_t)__cvta_generic_to_shared(p);
}
__device__ __forceinline__ void mma_tf32(float* c, const uint32_t* a,
                                         uint32_t b0, uint32_t b1) {
    asm volatile(
        "mma.sync.aligned.m16n8k8.row.col.f32.tf32.tf32.f32 "
        "{%0,%1,%2,%3}, {%4,%5,%6,%7}, {%8,%9}, {%0,%1,%2,%3};\n"
        : "+f"(c[0]), "+f"(c[1]), "+f"(c[2]), "+f"(c[3])
        : "r"(a[0]), "r"(a[1]), "r"(a[2]), "r"(a[3]), "r"(b0), "r"(b1));
}
__device__ __forceinline__ void ldsm_x4(uint32_t* r, uint32_t saddr) {
    asm volatile("ldmatrix.sync.aligned.m8n8.x4.shared.b16 {%0,%1,%2,%3}, [%4];"
        : "=r"(r[0]), "=r"(r[1]), "=r"(r[2]), "=r"(r[3]) : "r"(saddr));
}
__device__ __forceinline__ void cp16(uint32_t dst, const void* src) {
    asm volatile("cp.async.cg.shared.global [%0], [%1], 16;\n"
                 :: "r"(dst), "l"(src) : "memory");
}
__device__ __forceinline__ void cp4(uint32_t dst, const void* src) {
    asm volatile("cp.async.ca.shared.global [%0], [%1], 4;\n"
                 :: "r"(dst), "l"(src) : "memory");
}
__device__ __forceinline__ void cp_commit() {
    asm volatile("cp.async.commit_group;\n" ::: "memory");
}

// ---- Weight permute pre-kernel: Wp[(k>>4)*256 + n][perm(k&15)] = tf32(W[k][n])
__global__ void permW8(const float* w0, const float* w1, const float* w2, const float* w3,
                       const float* w4, const float* w5, const float* w6, const float* w7)
{
    const float* ws[8] = {w0, w1, w2, w3, w4, w5, w6, w7};
    int wi = blockIdx.y;
    int k  = blockIdx.x;          // 0..255
    int n  = threadIdx.x;         // 0..255
    float v = ws[wi][k * 256 + n];
    int kl = k & 15;
    int p  = ((kl & 3) << 2) | (kl >> 2);
    g_Wp[wi][(((k >> 4) * 256) + n) * 16 + p] = __uint_as_float(f2tf32(v));
}

// ---------------------------------------------------------------------------
// BM=128 BN=128 BK=32, 8 warps (4Mx2N, warp tile 32x64), 3-stage cp.async.
// AMODE: 0: a = X[addr] (async) ; 1: a = (1+X[addr])*X2[addr] (register-staged)
// EMODE: 0: OUT = acc+bias ; 1: OUT += acc+bias ; 2: OUT = res+acc+bias
// GATHER: 0: s0==1 (cp.async 16B) ; 1: scalar gather / attn (cp.async 4B)
// ---------------------------------------------------------------------------
template<int AMODE, int EMODE, int GATHER>
__global__ __launch_bounds__(256, 2)
void tgemm(const float* __restrict__ X, const float* __restrict__ X2,
           const float* __restrict__ Wp, const float* __restrict__ bias,
           const float* __restrict__ res, float* __restrict__ OUT, GDesc d)
{
    constexpr int ASTR  = 20;                 // A smem row stride (floats)
    constexpr int AFL   = 2 * 128 * ASTR;     // 5120 floats / stage
    constexpr int WFL   = 4096;               // 4096 floats / stage
    constexpr int STG_F = AFL + WFL;          // 9216 floats / stage
    constexpr int STG_B = STG_F * 4;          // bytes / stage
    extern __shared__ float sm[];
    __shared__ int rowAddr[128];

    const int tid = threadIdx.x;
    const int nb  = blockIdx.x;               // N-block: 0 / 1

    if (tid < 128) {
        int r = blockIdx.y * 128 + tid;
        int base = 0;
        #pragma unroll
        for (int i = 4; i >= 0; --i) {
            int dg = r % d.radix[i]; r /= d.radix[i];
            base += dg * d.rstride[i];
        }
        rowAddr[tid] = base;
    }
    __syncthreads();

    const int wid   = tid >> 5, lane = tid & 31;
    const int warpM = wid & 3,  warpN = wid >> 2;
    const int g     = lane >> 2, q    = lane & 3;
    const uint32_t smb = smem_u32(sm);

    // ---- per-thread running gather offsets (advance by 2*s1 per stage) ----
    int aoff4[4];  int ad4[4];    // GATHER==0 / AMODE==1: elem offs + smem byte offs
    int aoff16[16]; int ad16[16]; // GATHER==1
    if (GATHER == 0) {
        #pragma unroll
        for (int i = 0; i < 4; ++i) {
            int idx = tid + i * 256;              // 0..1023
            int row = idx >> 3, rem = idx & 7;
            int kg = rem >> 2, j = rem & 3;
            aoff4[i] = rowAddr[row] + kg * d.s1 + 4 * j;
            ad4[i]   = (kg * (128 * ASTR) + row * ASTR + 4 * j) * 4;
        }
    } else {
        #pragma unroll
        for (int i = 0; i < 16; ++i) {
            int idx = tid + i * 256;              // 0..4095
            int row = idx & 127, k = idx >> 7;    // rows contiguous in gmem
            aoff16[i] = rowAddr[row] + (k >> 4) * d.s1 + (k & 15) * d.s0;
            ad16[i]   = ((k >> 4) * (128 * ASTR) + row * ASTR + (k & 15)) * 4;
        }
    }
    // W: per-thread running offset (advance by 8192 floats per stage)
    int woff[4]; int wd4[4];
    #pragma unroll
    for (int i = 0; i < 4; ++i) {
        int idx4 = tid + i * 256;                 // 0..1023
        int kg = idx4 >> 9, off = idx4 & 511;
        woff[i] = (kg * 256 + nb * 128) * 16 + off * 4;
        wd4[i]  = (AFL + kg * 2048 + off * 4) * 4;
    }

    // ldmatrix per-thread fragment byte offsets (within a kg-block of A)
    const int m_ = lane >> 3, rt = lane & 7;
    int fo[2];
    #pragma unroll
    for (int mi = 0; mi < 2; ++mi)
        fo[mi] = ((warpM * 32 + mi * 16 + (m_ & 1) * 8 + rt) * ASTR + (m_ >> 1) * 4) * 4;

    float acc[2][8][4];
    #pragma unroll
    for (int mi = 0; mi < 2; ++mi)
        #pragma unroll
        for (int ni = 0; ni < 8; ++ni)
            #pragma unroll
            for (int j = 0; j < 4; ++j) acc[mi][ni][j] = 0.0f;

    // ---- stage issue: A (async or register-staged) + W (async) ----
    auto issueA = [&](int p) {
        uint32_t ab = smb + p * STG_B;
        if (AMODE == 0) {
            if (GATHER == 0) {
                #pragma unroll
                for (int i = 0; i < 4; ++i) {
                    cp16(ab + ad4[i], X + aoff4[i]);
                    aoff4[i] += 2 * d.s1;
                }
            } else {
                #pragma unroll
                for (int i = 0; i < 16; ++i) {
                    cp4(ab + ad16[i], X + aoff16[i]);
                    aoff16[i] += 2 * d.s1;
                }
            }
        } else {
            float* abf = sm + p * STG_F;
            #pragma unroll
            for (int i = 0; i < 4; ++i) {
                int ga = aoff4[i];
                aoff4[i] += 2 * d.s1;
                float4 v  = *reinterpret_cast<const float4*>(X + ga);
                float4 v2 = *reinterpret_cast<const float4*>(X2 + ga);
                v.x = (1.0f + v.x) * v2.x;  v.y = (1.0f + v.y) * v2.y;
                v.z = (1.0f + v.z) * v2.z;  v.w = (1.0f + v.w) * v2.w;
                *reinterpret_cast<float4*>(reinterpret_cast<char*>(abf) + ad4[i]) = v;
            }
        }
    };

    auto issueW = [&](int p) {
        uint32_t wbuf = smb + p * STG_B;
        #pragma unroll
        for (int i = 0; i < 4; ++i) {
            cp16(wbuf + wd4[i], Wp + woff[i]);
            woff[i] += 8192;                      // 2*256*16 floats per stage
        }
    };

    auto compute = [&](int p) {
        const uint32_t ab = smb + p * STG_B;
        const float* wbuf = sm + p * STG_F + AFL;
        #pragma unroll
        for (int kg = 0; kg < 2; ++kg) {
            uint32_t af[2][2][4];
            #pragma unroll
            for (int mi = 0; mi < 2; ++mi)
                #pragma unroll
                for (int kh = 0; kh < 2; ++kh)
                    ldsm_x4(af[mi][kh], ab + kg * (128 * ASTR * 4) + kh * 32 + fo[mi]);
            const float* W0 = wbuf + kg * 2048 + (warpN * 64) * 16 + 4 * q;
            #pragma unroll
            for (int ni = 0; ni < 8; ++ni) {
                float4 bv = *reinterpret_cast<const float4*>(W0 + (ni * 8 + g) * 16);
                uint32_t b0 = __float_as_uint(bv.x), b1 = __float_as_uint(bv.y);
                uint32_t b2 = __float_as_uint(bv.z), b3 = __float_as_uint(bv.w);
                #pragma unroll
                for (int mi = 0; mi < 2; ++mi) {
                    mma_tf32(acc[mi][ni], af[mi][0], b0, b1);
                    mma_tf32(acc[mi][ni], af[mi][1], b2, b3);
                }
            }
        }
    };

    // ---- 3-stage pipeline over 8 k32 stages ----
    issueA(0); issueW(0); cp_commit();
    issueA(1); issueW(1); cp_commit();

    #pragma unroll 1
    for (int s = 0; s < 8; ++s) {
        if (s < 7) asm volatile("cp.async.wait_group 1;\n" ::: "memory");
        else       asm volatile("cp.async.wait_group 0;\n" ::: "memory");
        __syncthreads();
        if (s < 6) { issueA((s + 2) % 3); issueW((s + 2) % 3); cp_commit(); }
        compute(s % 3);
    }

    // ---- epilogue: bias (+accumulate / +residual), scatter ----
    #pragma unroll
    for (int mi = 0; mi < 2; ++mi) {
        #pragma unroll
        for (int h = 0; h < 2; ++h) {
            int row  = warpM * 32 + mi * 16 + 8 * h + g;
            int base = rowAddr[row];
            #pragma unroll
            for (int ni = 0; ni < 8; ++ni) {
                int col = nb * 128 + warpN * 64 + ni * 8 + 2 * q;
                int a0  = base + (col >> 4) * d.s1 + (col & 15) * d.s0;
                int a1  = a0 + d.s0;
                float v0 = acc[mi][ni][2 * h + 0] + bias[col];
                float v1 = acc[mi][ni][2 * h + 1] + bias[col + 1];
                if (EMODE == 1) { v0 += OUT[a0]; v1 += OUT[a1]; }
                if (EMODE == 2) { v0 += res[a0]; v1 += res[a1]; }
                OUT[a0] = v0; OUT[a1] = v1;
            }
        }
    }
}

// ---------------------------------------------------------------------------

extern "C" void kernel_launch(void* const* d_in, const int* in_sizes, int n_in,
                              void* d_out, int out_size)
{
    (void)in_sizes; (void)n_in; (void)out_size;

    const float* x      = (const float*)d_in[0];
    const float* W_h    = (const float*)d_in[1];
    const float* b_h    = (const float*)d_in[2];
    const float* W_w    = (const float*)d_in[3];
    const float* b_w    = (const float*)d_in[4];
    const float* W_c    = (const float*)d_in[5];
    const float* b_c    = (const float*)d_in[6];
    const float* W_d    = (const float*)d_in[7];
    const float* b_d    = (const float*)d_in[8];
    const float* W_attn = (const float*)d_in[9];
    const float* b_attn = (const float*)d_in[10];
    const float* W_1    = (const float*)d_in[11];
    const float* b_1    = (const float*)d_in[12];
    const float* W_2    = (const float*)d_in[13];
    const float* b_2    = (const float*)d_in[14];
    const float* W_3    = (const float*)d_in[15];
    const float* b_3    = (const float*)d_in[16];
    float* out = (float*)d_out;

    float *bufA, *bufB, *bufC, *wp;
    cudaGetSymbolAddress((void**)&bufA, g_bufA);
    cudaGetSymbolAddress((void**)&bufB, g_bufB);
    cudaGetSymbolAddress((void**)&bufC, g_bufC);
    cudaGetSymbolAddress((void**)&wp,   g_Wp);
    const float* Wp_h    = wp + 0 * 65536;
    const float* Wp_w    = wp + 1 * 65536;
    const float* Wp_c    = wp + 2 * 65536;
    const float* Wp_d    = wp + 3 * 65536;
    const float* Wp_attn = wp + 4 * 65536;
    const float* Wp_1    = wp + 5 * 65536;
    const float* Wp_2    = wp + 6 * 65536;
    const float* Wp_3    = wp + 7 * 65536;

    constexpr int SMEM = 3 * 9216 * 4;   // 110592 B (3 stages x 36 KB)
    cudaFuncSetAttribute(tgemm<0,0,1>, cudaFuncAttributeMaxDynamicSharedMemorySize, SMEM);
    cudaFuncSetAttribute(tgemm<0,0,0>, cudaFuncAttributeMaxDynamicSharedMemorySize, SMEM);
    cudaFuncSetAttribute(tgemm<0,1,0>, cudaFuncAttributeMaxDynamicSharedMemorySize, SMEM);
    cudaFuncSetAttribute(tgemm<1,2,0>, cudaFuncAttributeMaxDynamicSharedMemorySize, SMEM);
    cudaFuncSetAttribute(tgemm<0,2,0>, cudaFuncAttributeMaxDynamicSharedMemorySize, SMEM);

    // x strides (elements): c=1, d=256, w=8192, h=262144, b=8388608
    GDesc d_att  = {{4, 2, 2, 32, 256}, {8388608, 4194304, 131072, 256, 1}, 262144, 8192};
    GDesc d_cont = {{1, 4, 32, 32, 32}, {0, 8388608, 262144, 8192, 256}, 16, 1};
    GDesc d_h    = {{4, 2, 32, 32, 16}, {8388608, 4194304, 8192, 256, 16}, 262144, 1};
    GDesc d_w    = {{4, 32, 2, 32, 16}, {8388608, 262144, 131072, 256, 16}, 8192, 1};
    GDesc d_d    = {{4, 32, 32, 2, 16}, {8388608, 262144, 8192, 4096, 16}, 256, 1};

    // permute + tf32(RNA)-round all 8 weight matrices (2 MB; trivial)
    permW8<<<dim3(256, 8), 256>>>(W_h, W_w, W_c, W_d, W_attn, W_1, W_2, W_3);

    dim3 grid(2, 1024), block(256);

    // Stage A (ip_mlp):
    // 1) t_att = attn(x)                          -> bufA
    tgemm<0,0,1><<<grid, block, SMEM>>>(x,    nullptr, Wp_attn, b_attn, nullptr, bufA, d_att);
    // 2) t_s = x @ W_c + b_c                      -> bufB
    tgemm<0,0,0><<<grid, block, SMEM>>>(x,    nullptr, Wp_c,    b_c,    nullptr, bufB, d_cont);
    // 3) t_s += x_h                               -> bufB
    tgemm<0,1,0><<<grid, block, SMEM>>>(x,    nullptr, Wp_h,    b_h,    nullptr, bufB, d_h);
    // 4) t_s += x_w                               -> bufB
    tgemm<0,1,0><<<grid, block, SMEM>>>(x,    nullptr, Wp_w,    b_w,    nullptr, bufB, d_w);
    // 5) x1 = x + ((1+t_att)*t_s) @ W_1 + b_1     -> bufC
    tgemm<1,2,0><<<grid, block, SMEM>>>(bufA, bufB,    Wp_1,    b_1,    x,       bufC, d_cont);
    // Stage B (tp_mlp):
    // 6) t_d = dgather(x1) @ W_d + b_d            -> bufA
    tgemm<0,0,0><<<grid, block, SMEM>>>(bufC, nullptr, Wp_d,    b_d,    nullptr, bufA, d_d);
    // 7) x2 = x1 + t_d @ W_2 + b_2                -> bufB
    tgemm<0,2,0><<<grid, block, SMEM>>>(bufA, nullptr, Wp_2,    b_2,    bufC,    bufB, d_cont);
    // Stage C:
    // 8) out = x2 + x2 @ W_3 + b_3                -> d_out
    tgemm<0,2,0><<<grid, block, SMEM>>>(bufB, nullptr, Wp_3,    b_3,    bufB,    out,  d_cont);
}